// round 15
// baseline (speedup 1.0000x reference)
#include <cuda_runtime.h>
#include <cuda_fp16.h>
#include <math.h>
#include <stdint.h>

#define SEQ   4096
#define EMBED 4096
#define HEADS 16
#define HD    256
#define ROT   64
#define NELEM (SEQ * EMBED)

// ---------------- scratch (allocation-free rule: __device__ globals) ----------
__device__ __half g_qh [NELEM];
__device__ __half g_kh [NELEM];
__device__ __half g_vh [NELEM];
__device__ __half g_ah [NELEM];
__device__ __half g_wqh[NELEM];
__device__ __half g_wkh[NELEM];
__device__ __half g_wvh[NELEM];
__device__ __half g_woh[NELEM];

// ==============================================================================
// helpers
// ==============================================================================
__device__ __forceinline__ void cp16(uint32_t dst, const void* src) {
    asm volatile("cp.async.cg.shared.global [%0], [%1], 16;" :: "r"(dst), "l"(src));
}

__device__ __forceinline__ void ldsm4(uint32_t* r, uint32_t a) {
    asm volatile("ldmatrix.sync.aligned.m8n8.x4.shared.b16 {%0,%1,%2,%3}, [%4];"
                 : "=r"(r[0]), "=r"(r[1]), "=r"(r[2]), "=r"(r[3]) : "r"(a));
}

__device__ __forceinline__ void ldsm4t(uint32_t* r, uint32_t a) {
    asm volatile("ldmatrix.sync.aligned.m8n8.x4.trans.shared.b16 {%0,%1,%2,%3}, [%4];"
                 : "=r"(r[0]), "=r"(r[1]), "=r"(r[2]), "=r"(r[3]) : "r"(a));
}

__device__ __forceinline__ void mma_f16(float* c, const uint32_t* a,
                                        uint32_t b0, uint32_t b1) {
    asm volatile(
        "mma.sync.aligned.m16n8k16.row.col.f32.f16.f16.f32 "
        "{%0,%1,%2,%3}, {%4,%5,%6,%7}, {%8,%9}, {%0,%1,%2,%3};"
        : "+f"(c[0]), "+f"(c[1]), "+f"(c[2]), "+f"(c[3])
        : "r"(a[0]), "r"(a[1]), "r"(a[2]), "r"(a[3]), "r"(b0), "r"(b1));
}

// ==============================================================================
// fused fp32 -> fp16 conversion: y-dim selects tensor (X + 4 weights)
// ==============================================================================
__global__ void cvt_f16_multi(const float* __restrict__ x0, __half* __restrict__ y0,
                              const float* __restrict__ x1, __half* __restrict__ y1,
                              const float* __restrict__ x2, __half* __restrict__ y2,
                              const float* __restrict__ x3, __half* __restrict__ y3,
                              const float* __restrict__ x4, __half* __restrict__ y4)
{
    const int z = blockIdx.y;
    const float* x = (z == 0) ? x0 : (z == 1) ? x1 : (z == 2) ? x2 : (z == 3) ? x3 : x4;
    __half*      y = (z == 0) ? y0 : (z == 1) ? y1 : (z == 2) ? y2 : (z == 3) ? y3 : y4;
    const int i = blockIdx.x * blockDim.x + threadIdx.x;
    float4 v = ((const float4*)x)[i];
    ((half2*)y)[2 * i]     = __floats2half2_rn(v.x, v.y);
    ((half2*)y)[2 * i + 1] = __floats2half2_rn(v.z, v.w);
}

// ==============================================================================
// RoPE rotation on an fp32 column pair (col even)
// ==============================================================================
__device__ __forceinline__ void rope2(float& c0, float& c1, int row, int col)
{
    const int hd = col & 255;
    if (hd < ROT) {
        const float inv = powf(10000.f, -(float)(hd >> 1) / 32.f);
        float sn, cs;
        sincosf((float)row * inv, &sn, &cs);
        const float x = c0, y = c1;
        c0 = x * cs - y * sn;
        c1 = y * cs + x * sn;
    }
}

// ==============================================================================
// fp16 tensor-core GEMM (NT): C = A * B^T. 128x128 tile, BK=64, 3-stage
// cp.async pipeline, 8 warps (256 thr), warp tile 32x64, 128 regs/thread,
// 110.6KB smem -> TWO CTAs per SM. NEW: persistent grids (304 CTAs loop over
// tiles) remove wave-quantization tails.
// epilogue modes: 0 = fp32 C, 1 = rope + fp16, 2 = fp16 plain
// ==============================================================================
#define HSTR  144
#define SOFFB (128 * HSTR)                  // 18432
#define SSTG  (256 * HSTR)                  // 36864 per stage
#define GEMM_SMEM (3 * SSTG)                // 110592
#define GTHR  256
#define GEMM_GRID 304                        // 152 SMs x 2 CTAs

__device__ __forceinline__ void gemm_body(const __half* __restrict__ A,
                                          const __half* __restrict__ B,
                                          uint32_t sb, int m0, int n0,
                                          int mode, float* Cf, __half* Ch)
{
    const int tid  = threadIdx.x;
    const int lane = tid & 31;
    const int warp = tid >> 5;
    const int wm   = warp & 3;              // 32-row slab (4)
    const int wn   = warp >> 2;             // 64-col slab (2)

    float acc[2][8][4];
#pragma unroll
    for (int i = 0; i < 2; i++)
#pragma unroll
        for (int j = 0; j < 8; j++)
#pragma unroll
            for (int r = 0; r < 4; r++) acc[i][j][r] = 0.f;

    auto load_stage = [&](int stage, int kt) {
        const uint32_t st = sb + stage * SSTG;
#pragma unroll
        for (int i = 0; i < 4; i++) {
            const int f = tid + 256 * i;
            const int r = f >> 3, c = f & 7;
            cp16(st + r * HSTR + c * 16,
                 A + (size_t)(m0 + r) * 4096 + kt + c * 8);
            cp16(st + SOFFB + r * HSTR + c * 16,
                 B + (size_t)(n0 + r) * 4096 + kt + c * 8);
        }
        asm volatile("cp.async.commit_group;");
    };

    load_stage(0, 0);
    load_stage(1, 64);

    const uint32_t arow = (lane & 15) * HSTR + (lane >> 4) * 16;
    const uint32_t brow = ((lane & 7) + ((lane >> 4) & 1) * 8) * HSTR
                        + ((lane >> 3) & 1) * 16;
    const int NT = 4096 / 64;   // 64

    int stage = 0;
    for (int t = 0; t < NT; t++) {
        if (t < NT - 1) asm volatile("cp.async.wait_group 1;");
        else            asm volatile("cp.async.wait_group 0;");
        __syncthreads();
        if (t + 2 < NT) {
            int ns = stage + 2; if (ns >= 3) ns -= 3;
            load_stage(ns, (t + 2) * 64);
        }

        const uint32_t ab = sb + stage * SSTG + (wm * 32) * HSTR;
        const uint32_t bb = sb + stage * SSTG + SOFFB + (wn * 64) * HSTR;

#pragma unroll
        for (int ks = 0; ks < 4; ks++) {
            const int kb = ks * 32;
            uint32_t af[2][4], bf[4][4];
            ldsm4(af[0], ab + arow + kb);
            ldsm4(af[1], ab + 16 * HSTR + arow + kb);
            ldsm4(bf[0], bb + brow + kb);
            ldsm4(bf[1], bb + 16 * HSTR + brow + kb);
            ldsm4(bf[2], bb + 32 * HSTR + brow + kb);
            ldsm4(bf[3], bb + 48 * HSTR + brow + kb);
#pragma unroll
            for (int np = 0; np < 4; np++)
#pragma unroll
                for (int mt = 0; mt < 2; mt++) {
                    mma_f16(acc[mt][np * 2],     af[mt], bf[np][0], bf[np][1]);
                    mma_f16(acc[mt][np * 2 + 1], af[mt], bf[np][2], bf[np][3]);
                }
        }
        if (++stage == 3) stage = 0;
    }

    const int g  = lane >> 2;
    const int qd = lane & 3;
#pragma unroll
    for (int mt = 0; mt < 2; mt++) {
        const int r0 = m0 + wm * 32 + mt * 16 + g;
#pragma unroll
        for (int nt = 0; nt < 8; nt++) {
            const int col = n0 + wn * 64 + nt * 8 + qd * 2;
#pragma unroll
            for (int half = 0; half < 2; half++) {
                const int row = r0 + half * 8;
                float c0 = acc[mt][nt][half * 2], c1 = acc[mt][nt][half * 2 + 1];
                if (mode == 0) {
                    *(float2*)&Cf[(size_t)row * 4096 + col] = make_float2(c0, c1);
                } else if (mode == 1) {
                    rope2(c0, c1, row, col);
                    ((half2*)Ch)[((size_t)row * 4096 + col) >> 1] =
                        __floats2half2_rn(c0, c1);
                } else {
                    ((half2*)Ch)[((size_t)row * 4096 + col) >> 1] =
                        __floats2half2_rn(c0, c1);
                }
            }
        }
    }
}

// persistent: 3*1024 tiles; z = tile>>10 selects (B, C, mode)
__global__ __launch_bounds__(GTHR, 2)
void gemm_f16_qkv(const __half* __restrict__ A,
                  const __half* __restrict__ Bq, const __half* __restrict__ Bk,
                  const __half* __restrict__ Bv,
                  __half* __restrict__ qh, __half* __restrict__ kh,
                  __half* __restrict__ vh)
{
    extern __shared__ __align__(16) char smg[];
    const uint32_t sb = (uint32_t)__cvta_generic_to_shared(smg);
    for (int t = blockIdx.x; t < 3 * 1024; t += gridDim.x) {
        const int z   = t >> 10;
        const int rem = t & 1023;
        const __half* B = (z == 0) ? Bq : (z == 1) ? Bk : Bv;
        __half* C      = (z == 0) ? qh : (z == 1) ? kh : vh;
        gemm_body(A, B, sb, (rem >> 5) * 128, (rem & 31) * 128,
                  (z == 2) ? 2 : 1, nullptr, C);
        __syncthreads();   // next tile's stage-0 writes vs this tile's last reads
    }
}

// persistent: 1024 tiles, fp32 output
__global__ __launch_bounds__(GTHR, 2)
void gemm_f16_out(const __half* __restrict__ A, const __half* __restrict__ B,
                  float* __restrict__ C)
{
    extern __shared__ __align__(16) char smg[];
    const uint32_t sb = (uint32_t)__cvta_generic_to_shared(smg);
    for (int t = blockIdx.x; t < 1024; t += gridDim.x) {
        gemm_body(A, B, sb, (t >> 5) * 128, (t & 31) * 128, 0, C, nullptr);
        __syncthreads();
    }
}

// ==============================================================================
// Tensor-core causal flash attention (round-14 version, validated 2210us run).
// QK: single fp16 product. PV: fp16. Softmax fp32. K/V share one smem buffer;
// 94.7KB smem -> 2 CTAs/SM.
// ==============================================================================
#define QSTR 528
#define PSTR 144
#define S_Q    0
#define S_KV   33792
#define S_SB   67584
#define S_P    84992
#define S_CORR 94208
#define S_LINV 94464
#define ATT_SMEM 94720

__global__ __launch_bounds__(256, 2)
void attn_mma(const __half* __restrict__ Qh, const __half* __restrict__ Kh,
              const __half* __restrict__ Vh, __half* __restrict__ Oh)
{
    extern __shared__ __align__(16) char sm[];
    const uint32_t sb = (uint32_t)__cvta_generic_to_shared(sm);
    float* SBf    = (float*)(sm + S_SB);
    float* corr_s = (float*)(sm + S_CORR);
    float* linv_s = (float*)(sm + S_LINV);

    const int tid   = threadIdx.x;
    const int lane  = tid & 31;
    const int wid   = tid >> 5;
    const int grp   = wid >> 2;
    const int slice = (wid & 3) * 16;
    const int g     = lane >> 2;
    const int qd    = lane & 3;

    const int h    = blockIdx.y;
    const int m0   = ((int)gridDim.x - 1 - (int)blockIdx.x) * 64;
    const int cb   = h * HD;
    const int doff = grp * 128;

    for (int f = tid; f < 2048; f += 256) {
        const int r = f >> 5, c = f & 31;
        cp16(sb + S_Q + r * QSTR + c * 16,
             Qh + (size_t)(m0 + r) * EMBED + cb + c * 8);
    }

    float of[16][4];
#pragma unroll
    for (int j = 0; j < 16; j++)
#pragma unroll
        for (int r = 0; r < 4; r++) of[j][r] = 0.f;
    float mr0 = -1e30f, mr1 = -1e30f, l0 = 0.f, l1 = 0.f;

    const int ntl = m0 / 64 + 1;
    for (int t = 0; t < ntl; t++) {
        const int n0 = t * 64;

        for (int f = tid; f < 2048; f += 256) {
            const int r = f >> 5, c = f & 31;
            cp16(sb + S_KV + r * QSTR + c * 16,
                 Kh + (size_t)(n0 + r) * EMBED + cb + c * 8);
        }
        asm volatile("cp.async.commit_group;");
        asm volatile("cp.async.wait_group 0;");
        __syncthreads();

        float sf[8][4];
#pragma unroll
        for (int nt = 0; nt < 8; nt++)
#pragma unroll
            for (int r = 0; r < 4; r++) sf[nt][r] = 0.f;

        const uint32_t qa = sb + S_Q + (slice + (lane & 15)) * QSTR + (lane >> 4) * 16;
#pragma unroll
        for (int kc = 0; kc < 8; kc++) {
            const int dby = (doff + kc * 16) * 2;
            uint32_t qf[4];
            ldsm4(qf, qa + dby);
#pragma unroll
            for (int kg = 0; kg < 4; kg++) {
                const int key = kg * 16 + (lane & 7) + ((lane >> 4) & 1) * 8;
                const uint32_t ba = sb + S_KV + key * QSTR + dby + ((lane >> 3) & 1) * 16;
                uint32_t kf[4];
                ldsm4(kf, ba);
                mma_f16(sf[2 * kg],     qf, kf[0], kf[1]);
                mma_f16(sf[2 * kg + 1], qf, kf[2], kf[3]);
            }
        }

        if (grp == 1) {
#pragma unroll
            for (int nt = 0; nt < 8; nt++) {
                const int col = nt * 8 + qd * 2;
                *(float2*)&SBf[(slice + g) * 68 + col]     = make_float2(sf[nt][0], sf[nt][1]);
                *(float2*)&SBf[(slice + g + 8) * 68 + col] = make_float2(sf[nt][2], sf[nt][3]);
            }
        }
        __syncthreads();

        for (int f = tid; f < 2048; f += 256) {
            const int r = f >> 5, c = f & 31;
            cp16(sb + S_KV + r * QSTR + c * 16,
                 Vh + (size_t)(n0 + r) * EMBED + cb + c * 8);
        }
        asm volatile("cp.async.commit_group;");

        if (grp == 0) {
            const int row0 = m0 + slice + g, row1 = row0 + 8;
            float px0 = -1e30f, px1 = -1e30f;
#pragma unroll
            for (int nt = 0; nt < 8; nt++) {
                const int col = nt * 8 + qd * 2;
                const float2 b0 = *(float2*)&SBf[(slice + g) * 68 + col];
                const float2 b1 = *(float2*)&SBf[(slice + g + 8) * 68 + col];
                const int cg = n0 + col;
                sf[nt][0] = (cg     <= row0) ? (sf[nt][0] + b0.x) * 0.0625f : -1e30f;
                sf[nt][1] = (cg + 1 <= row0) ? (sf[nt][1] + b0.y) * 0.0625f : -1e30f;
                sf[nt][2] = (cg     <= row1) ? (sf[nt][2] + b1.x) * 0.0625f : -1e30f;
                sf[nt][3] = (cg + 1 <= row1) ? (sf[nt][3] + b1.y) * 0.0625f : -1e30f;
                px0 = fmaxf(px0, fmaxf(sf[nt][0], sf[nt][1]));
                px1 = fmaxf(px1, fmaxf(sf[nt][2], sf[nt][3]));
            }
            px0 = fmaxf(px0, __shfl_xor_sync(0xffffffffu, px0, 1));
            px0 = fmaxf(px0, __shfl_xor_sync(0xffffffffu, px0, 2));
            px1 = fmaxf(px1, __shfl_xor_sync(0xffffffffu, px1, 1));
            px1 = fmaxf(px1, __shfl_xor_sync(0xffffffffu, px1, 2));
            const float mn0 = fmaxf(mr0, px0), mn1 = fmaxf(mr1, px1);
            const float cr0 = __expf(mr0 - mn0), cr1 = __expf(mr1 - mn1);
            mr0 = mn0; mr1 = mn1;
            float s0 = 0.f, s1 = 0.f;
#pragma unroll
            for (int nt = 0; nt < 8; nt++) {
                const float p0 = __expf(sf[nt][0] - mn0);
                const float p1 = __expf(sf[nt][1] - mn0);
                const float p2 = __expf(sf[nt][2] - mn1);
                const float p3 = __expf(sf[nt][3] - mn1);
                s0 += p0 + p1; s1 += p2 + p3;
                const int col = nt * 8 + qd * 2;
                *(half2*)(sm + S_P + (slice + g) * PSTR + col * 2)     = __floats2half2_rn(p0, p1);
                *(half2*)(sm + S_P + (slice + g + 8) * PSTR + col * 2) = __floats2half2_rn(p2, p3);
            }
            s0 += __shfl_xor_sync(0xffffffffu, s0, 1);
            s0 += __shfl_xor_sync(0xffffffffu, s0, 2);
            s1 += __shfl_xor_sync(0xffffffffu, s1, 1);
            s1 += __shfl_xor_sync(0xffffffffu, s1, 2);
            l0 = l0 * cr0 + s0;
            l1 = l1 * cr1 + s1;
            if (qd == 0) { corr_s[slice + g] = cr0; corr_s[slice + g + 8] = cr1; }
        }
        asm volatile("cp.async.wait_group 0;");
        __syncthreads();

        {
            const float c0 = corr_s[slice + g], c1 = corr_s[slice + g + 8];
#pragma unroll
            for (int j = 0; j < 16; j++) {
                of[j][0] *= c0; of[j][1] *= c0; of[j][2] *= c1; of[j][3] *= c1;
            }
        }
#pragma unroll
        for (int kc = 0; kc < 4; kc++) {
            uint32_t pa[4];
            ldsm4(pa, sb + S_P + (slice + (lane & 15)) * PSTR + kc * 32 + (lane >> 4) * 16);
            const int key = kc * 16 + (lane & 7) + ((lane >> 3) & 1) * 8;
#pragma unroll
            for (int jj = 0; jj < 8; jj++) {
                uint32_t vb[4];
                ldsm4t(vb, sb + S_KV + key * QSTR + (doff + jj * 16) * 2 + ((lane >> 4) & 1) * 16);
                mma_f16(of[2 * jj],     pa, vb[0], vb[1]);
                mma_f16(of[2 * jj + 1], pa, vb[2], vb[3]);
            }
        }
        __syncthreads();
    }

    if (grp == 0 && qd == 0) {
        linv_s[slice + g]     = 1.f / l0;
        linv_s[slice + g + 8] = 1.f / l1;
    }
    __syncthreads();
    const float ia = linv_s[slice + g], ib = linv_s[slice + g + 8];
    const int row0 = m0 + slice + g;
#pragma unroll
    for (int nt = 0; nt < 16; nt++) {
        const int col = cb + doff + nt * 8 + qd * 2;
        ((half2*)Oh)[((size_t)row0 * EMBED + col) >> 1] =
            __floats2half2_rn(of[nt][0] * ia, of[nt][1] * ia);
        ((half2*)Oh)[((size_t)(row0 + 8) * EMBED + col) >> 1] =
            __floats2half2_rn(of[nt][2] * ib, of[nt][3] * ib);
    }
}

// ==============================================================================
// launch
// ==============================================================================
extern "C" void kernel_launch(void* const* d_in, const int* in_sizes, int n_in,
                              void* d_out, int out_size)
{
    (void)in_sizes; (void)n_in; (void)out_size;
    const float* X  = (const float*)d_in[0];
    const float* Wq = (const float*)d_in[1];
    const float* Wk = (const float*)d_in[2];
    const float* Wv = (const float*)d_in[3];
    const float* Wo = (const float*)d_in[4];
    float* out = (float*)d_out;

    __half *qh, *kh, *vh, *ah, *wqh, *wkh, *wvh, *woh;
    cudaGetSymbolAddress((void**)&qh,  g_qh);
    cudaGetSymbolAddress((void**)&kh,  g_kh);
    cudaGetSymbolAddress((void**)&vh,  g_vh);
    cudaGetSymbolAddress((void**)&ah,  g_ah);
    cudaGetSymbolAddress((void**)&wqh, g_wqh);
    cudaGetSymbolAddress((void**)&wkh, g_wkh);
    cudaGetSymbolAddress((void**)&wvh, g_wvh);
    cudaGetSymbolAddress((void**)&woh, g_woh);

    cudaFuncSetAttribute(gemm_f16_out,
                         cudaFuncAttributeMaxDynamicSharedMemorySize, GEMM_SMEM);
    cudaFuncSetAttribute(gemm_f16_qkv,
                         cudaFuncAttributeMaxDynamicSharedMemorySize, GEMM_SMEM);
    cudaFuncSetAttribute(attn_mma,
                         cudaFuncAttributeMaxDynamicSharedMemorySize, ATT_SMEM);

    const int CVB = NELEM / 4 / 256;
    dim3 gc(CVB, 5);
    cvt_f16_multi<<<gc, 256>>>(X, ah, Wq, wqh, Wk, wkh, Wv, wvh, Wo, woh);

    gemm_f16_qkv<<<GEMM_GRID, GTHR, GEMM_SMEM>>>(ah, wqh, wkh, wvh, qh, kh, vh);

    dim3 ga(SEQ / 64, HEADS);
    attn_mma<<<ga, 256, ATT_SMEM>>>(qh, kh, vh, ah);

    gemm_f16_out<<<GEMM_GRID, GTHR, GEMM_SMEM>>>(ah, woh, out);
}

// round 16
// speedup vs baseline: 1.5598x; 1.5598x over previous
#include <cuda_runtime.h>
#include <cuda_fp16.h>
#include <math.h>
#include <stdint.h>

#define SEQ   4096
#define EMBED 4096
#define HEADS 16
#define HD    256
#define ROT   64
#define NELEM (SEQ * EMBED)

// ---------------- scratch (allocation-free rule: __device__ globals) ----------
__device__ __half g_qh [NELEM];
__device__ __half g_kh [NELEM];
__device__ __half g_vh [NELEM];
__device__ __half g_ah [NELEM];
__device__ __half g_wqh[NELEM];
__device__ __half g_wkh[NELEM];
__device__ __half g_wvh[NELEM];
__device__ __half g_woh[NELEM];

// ==============================================================================
// helpers
// ==============================================================================
__device__ __forceinline__ void cp16(uint32_t dst, const void* src) {
    asm volatile("cp.async.cg.shared.global [%0], [%1], 16;" :: "r"(dst), "l"(src));
}

__device__ __forceinline__ void ldsm4(uint32_t* r, uint32_t a) {
    asm volatile("ldmatrix.sync.aligned.m8n8.x4.shared.b16 {%0,%1,%2,%3}, [%4];"
                 : "=r"(r[0]), "=r"(r[1]), "=r"(r[2]), "=r"(r[3]) : "r"(a));
}

__device__ __forceinline__ void ldsm4t(uint32_t* r, uint32_t a) {
    asm volatile("ldmatrix.sync.aligned.m8n8.x4.trans.shared.b16 {%0,%1,%2,%3}, [%4];"
                 : "=r"(r[0]), "=r"(r[1]), "=r"(r[2]), "=r"(r[3]) : "r"(a));
}

__device__ __forceinline__ void mma_f16(float* c, const uint32_t* a,
                                        uint32_t b0, uint32_t b1) {
    asm volatile(
        "mma.sync.aligned.m16n8k16.row.col.f32.f16.f16.f32 "
        "{%0,%1,%2,%3}, {%4,%5,%6,%7}, {%8,%9}, {%0,%1,%2,%3};"
        : "+f"(c[0]), "+f"(c[1]), "+f"(c[2]), "+f"(c[3])
        : "r"(a[0]), "r"(a[1]), "r"(a[2]), "r"(a[3]), "r"(b0), "r"(b1));
}

// ==============================================================================
// fused fp32 -> fp16 conversion: y-dim selects tensor; 2 x float4 per thread
// ==============================================================================
__global__ void cvt_f16_multi(const float* __restrict__ x0, __half* __restrict__ y0,
                              const float* __restrict__ x1, __half* __restrict__ y1,
                              const float* __restrict__ x2, __half* __restrict__ y2,
                              const float* __restrict__ x3, __half* __restrict__ y3,
                              const float* __restrict__ x4, __half* __restrict__ y4)
{
    const int z = blockIdx.y;
    const float* x = (z == 0) ? x0 : (z == 1) ? x1 : (z == 2) ? x2 : (z == 3) ? x3 : x4;
    __half*      y = (z == 0) ? y0 : (z == 1) ? y1 : (z == 2) ? y2 : (z == 3) ? y3 : y4;
    const int i = blockIdx.x * blockDim.x + threadIdx.x;
#pragma unroll
    for (int u = 0; u < 2; u++) {
        const int e = 2 * i + u;
        float4 v = ((const float4*)x)[e];
        ((half2*)y)[2 * e]     = __floats2half2_rn(v.x, v.y);
        ((half2*)y)[2 * e + 1] = __floats2half2_rn(v.z, v.w);
    }
}

// ==============================================================================
// RoPE rotation on an fp32 column pair (col even); exp2f instead of powf
// ==============================================================================
__device__ __forceinline__ void rope2(float& c0, float& c1, int row, int col)
{
    const int hd = col & 255;
    if (hd < ROT) {
        // 10000^(-j/32) == exp2f(-j * log2(10000)/32)
        const float inv = exp2f((float)(hd >> 1) * -0.41524101186092f);
        float sn, cs;
        sincosf((float)row * inv, &sn, &cs);
        const float x = c0, y = c1;
        c0 = x * cs - y * sn;
        c1 = y * cs + x * sn;
    }
}

// ==============================================================================
// fp16 tensor-core GEMM (NT): C = A * B^T. 128x128 block, BK=64, 3-stage
// cp.async pipeline, 8 warps (256 thr), warp tile 32x64, 128 regs/thread,
// 110.6KB smem -> TWO CTAs per SM. (round-14 config: proven 371us/GEMM,
// multi-CTA launch — persistent variant regressed in round 15, reverted)
// epilogue modes: 0 = fp32 C, 1 = rope + fp16, 2 = fp16 plain
// ==============================================================================
#define HSTR  144
#define SOFFB (128 * HSTR)                  // 18432
#define SSTG  (256 * HSTR)                  // 36864 per stage
#define GEMM_SMEM (3 * SSTG)                // 110592
#define GTHR  256

__device__ __forceinline__ void gemm_body(const __half* __restrict__ A,
                                          const __half* __restrict__ B,
                                          uint32_t sb, int m0, int n0,
                                          int mode, float* Cf, __half* Ch)
{
    const int tid  = threadIdx.x;
    const int lane = tid & 31;
    const int warp = tid >> 5;
    const int wm   = warp & 3;              // 32-row slab (4)
    const int wn   = warp >> 2;             // 64-col slab (2)

    float acc[2][8][4];
#pragma unroll
    for (int i = 0; i < 2; i++)
#pragma unroll
        for (int j = 0; j < 8; j++)
#pragma unroll
            for (int r = 0; r < 4; r++) acc[i][j][r] = 0.f;

    auto load_stage = [&](int stage, int kt) {
        const uint32_t st = sb + stage * SSTG;
#pragma unroll
        for (int i = 0; i < 4; i++) {
            const int f = tid + 256 * i;
            const int r = f >> 3, c = f & 7;
            cp16(st + r * HSTR + c * 16,
                 A + (size_t)(m0 + r) * 4096 + kt + c * 8);
            cp16(st + SOFFB + r * HSTR + c * 16,
                 B + (size_t)(n0 + r) * 4096 + kt + c * 8);
        }
        asm volatile("cp.async.commit_group;");
    };

    load_stage(0, 0);
    load_stage(1, 64);

    const uint32_t arow = (lane & 15) * HSTR + (lane >> 4) * 16;
    const uint32_t brow = ((lane & 7) + ((lane >> 4) & 1) * 8) * HSTR
                        + ((lane >> 3) & 1) * 16;
    const int NT = 4096 / 64;   // 64

    int stage = 0;
    for (int t = 0; t < NT; t++) {
        if (t < NT - 1) asm volatile("cp.async.wait_group 1;");
        else            asm volatile("cp.async.wait_group 0;");
        __syncthreads();
        if (t + 2 < NT) {
            int ns = stage + 2; if (ns >= 3) ns -= 3;
            load_stage(ns, (t + 2) * 64);
        }

        const uint32_t ab = sb + stage * SSTG + (wm * 32) * HSTR;
        const uint32_t bb = sb + stage * SSTG + SOFFB + (wn * 64) * HSTR;

#pragma unroll
        for (int ks = 0; ks < 4; ks++) {
            const int kb = ks * 32;
            uint32_t af[2][4], bf[4][4];
            ldsm4(af[0], ab + arow + kb);
            ldsm4(af[1], ab + 16 * HSTR + arow + kb);
            ldsm4(bf[0], bb + brow + kb);
            ldsm4(bf[1], bb + 16 * HSTR + brow + kb);
            ldsm4(bf[2], bb + 32 * HSTR + brow + kb);
            ldsm4(bf[3], bb + 48 * HSTR + brow + kb);
#pragma unroll
            for (int np = 0; np < 4; np++)
#pragma unroll
                for (int mt = 0; mt < 2; mt++) {
                    mma_f16(acc[mt][np * 2],     af[mt], bf[np][0], bf[np][1]);
                    mma_f16(acc[mt][np * 2 + 1], af[mt], bf[np][2], bf[np][3]);
                }
        }
        if (++stage == 3) stage = 0;
    }

    const int g  = lane >> 2;
    const int qd = lane & 3;
#pragma unroll
    for (int mt = 0; mt < 2; mt++) {
        const int r0 = m0 + wm * 32 + mt * 16 + g;
#pragma unroll
        for (int nt = 0; nt < 8; nt++) {
            const int col = n0 + wn * 64 + nt * 8 + qd * 2;
#pragma unroll
            for (int half = 0; half < 2; half++) {
                const int row = r0 + half * 8;
                float c0 = acc[mt][nt][half * 2], c1 = acc[mt][nt][half * 2 + 1];
                if (mode == 0) {
                    *(float2*)&Cf[(size_t)row * 4096 + col] = make_float2(c0, c1);
                } else if (mode == 1) {
                    rope2(c0, c1, row, col);
                    ((half2*)Ch)[((size_t)row * 4096 + col) >> 1] =
                        __floats2half2_rn(c0, c1);
                } else {
                    ((half2*)Ch)[((size_t)row * 4096 + col) >> 1] =
                        __floats2half2_rn(c0, c1);
                }
            }
        }
    }
}

__global__ __launch_bounds__(GTHR, 2)
void gemm_f16_out(const __half* __restrict__ A, const __half* __restrict__ B,
                  float* __restrict__ C)
{
    extern __shared__ __align__(16) char smg[];
    gemm_body(A, B, (uint32_t)__cvta_generic_to_shared(smg),
              blockIdx.y * 128, blockIdx.x * 128, 0, C, nullptr);
}

__global__ __launch_bounds__(GTHR, 2)
void gemm_f16_qkv(const __half* __restrict__ A,
                  const __half* __restrict__ Bq, const __half* __restrict__ Bk,
                  const __half* __restrict__ Bv,
                  __half* __restrict__ qh, __half* __restrict__ kh,
                  __half* __restrict__ vh)
{
    extern __shared__ __align__(16) char smg[];
    const int z = blockIdx.z;
    const __half* B = (z == 0) ? Bq : (z == 1) ? Bk : Bv;
    __half* C      = (z == 0) ? qh : (z == 1) ? kh : vh;
    gemm_body(A, B, (uint32_t)__cvta_generic_to_shared(smg),
              blockIdx.y * 128, blockIdx.x * 128, (z == 2) ? 2 : 1,
              nullptr, C);
}

// ==============================================================================
// Tensor-core causal flash attention (round-14 version, validated 2210us run).
// QK: single fp16 product. PV: fp16. Softmax fp32. K/V share one smem buffer
// (K dead after QK -> V loads during softmax); 94.7KB smem -> 2 CTAs/SM.
// ==============================================================================
#define QSTR 528
#define PSTR 144
#define S_Q    0
#define S_KV   33792
#define S_SB   67584
#define S_P    84992
#define S_CORR 94208
#define S_LINV 94464
#define ATT_SMEM 94720

__global__ __launch_bounds__(256, 2)
void attn_mma(const __half* __restrict__ Qh, const __half* __restrict__ Kh,
              const __half* __restrict__ Vh, __half* __restrict__ Oh)
{
    extern __shared__ __align__(16) char sm[];
    const uint32_t sb = (uint32_t)__cvta_generic_to_shared(sm);
    float* SBf    = (float*)(sm + S_SB);
    float* corr_s = (float*)(sm + S_CORR);
    float* linv_s = (float*)(sm + S_LINV);

    const int tid   = threadIdx.x;
    const int lane  = tid & 31;
    const int wid   = tid >> 5;
    const int grp   = wid >> 2;
    const int slice = (wid & 3) * 16;
    const int g     = lane >> 2;
    const int qd    = lane & 3;

    const int h    = blockIdx.y;
    const int m0   = ((int)gridDim.x - 1 - (int)blockIdx.x) * 64;
    const int cb   = h * HD;
    const int doff = grp * 128;

    for (int f = tid; f < 2048; f += 256) {
        const int r = f >> 5, c = f & 31;
        cp16(sb + S_Q + r * QSTR + c * 16,
             Qh + (size_t)(m0 + r) * EMBED + cb + c * 8);
    }

    float of[16][4];
#pragma unroll
    for (int j = 0; j < 16; j++)
#pragma unroll
        for (int r = 0; r < 4; r++) of[j][r] = 0.f;
    float mr0 = -1e30f, mr1 = -1e30f, l0 = 0.f, l1 = 0.f;

    const int ntl = m0 / 64 + 1;
    for (int t = 0; t < ntl; t++) {
        const int n0 = t * 64;

        for (int f = tid; f < 2048; f += 256) {
            const int r = f >> 5, c = f & 31;
            cp16(sb + S_KV + r * QSTR + c * 16,
                 Kh + (size_t)(n0 + r) * EMBED + cb + c * 8);
        }
        asm volatile("cp.async.commit_group;");
        asm volatile("cp.async.wait_group 0;");
        __syncthreads();

        float sf[8][4];
#pragma unroll
        for (int nt = 0; nt < 8; nt++)
#pragma unroll
            for (int r = 0; r < 4; r++) sf[nt][r] = 0.f;

        const uint32_t qa = sb + S_Q + (slice + (lane & 15)) * QSTR + (lane >> 4) * 16;
#pragma unroll
        for (int kc = 0; kc < 8; kc++) {
            const int dby = (doff + kc * 16) * 2;
            uint32_t qf[4];
            ldsm4(qf, qa + dby);
#pragma unroll
            for (int kg = 0; kg < 4; kg++) {
                const int key = kg * 16 + (lane & 7) + ((lane >> 4) & 1) * 8;
                const uint32_t ba = sb + S_KV + key * QSTR + dby + ((lane >> 3) & 1) * 16;
                uint32_t kf[4];
                ldsm4(kf, ba);
                mma_f16(sf[2 * kg],     qf, kf[0], kf[1]);
                mma_f16(sf[2 * kg + 1], qf, kf[2], kf[3]);
            }
        }

        if (grp == 1) {
#pragma unroll
            for (int nt = 0; nt < 8; nt++) {
                const int col = nt * 8 + qd * 2;
                *(float2*)&SBf[(slice + g) * 68 + col]     = make_float2(sf[nt][0], sf[nt][1]);
                *(float2*)&SBf[(slice + g + 8) * 68 + col] = make_float2(sf[nt][2], sf[nt][3]);
            }
        }
        __syncthreads();

        for (int f = tid; f < 2048; f += 256) {
            const int r = f >> 5, c = f & 31;
            cp16(sb + S_KV + r * QSTR + c * 16,
                 Vh + (size_t)(n0 + r) * EMBED + cb + c * 8);
        }
        asm volatile("cp.async.commit_group;");

        if (grp == 0) {
            const int row0 = m0 + slice + g, row1 = row0 + 8;
            float px0 = -1e30f, px1 = -1e30f;
#pragma unroll
            for (int nt = 0; nt < 8; nt++) {
                const int col = nt * 8 + qd * 2;
                const float2 b0 = *(float2*)&SBf[(slice + g) * 68 + col];
                const float2 b1 = *(float2*)&SBf[(slice + g + 8) * 68 + col];
                const int cg = n0 + col;
                sf[nt][0] = (cg     <= row0) ? (sf[nt][0] + b0.x) * 0.0625f : -1e30f;
                sf[nt][1] = (cg + 1 <= row0) ? (sf[nt][1] + b0.y) * 0.0625f : -1e30f;
                sf[nt][2] = (cg     <= row1) ? (sf[nt][2] + b1.x) * 0.0625f : -1e30f;
                sf[nt][3] = (cg + 1 <= row1) ? (sf[nt][3] + b1.y) * 0.0625f : -1e30f;
                px0 = fmaxf(px0, fmaxf(sf[nt][0], sf[nt][1]));
                px1 = fmaxf(px1, fmaxf(sf[nt][2], sf[nt][3]));
            }
            px0 = fmaxf(px0, __shfl_xor_sync(0xffffffffu, px0, 1));
            px0 = fmaxf(px0, __shfl_xor_sync(0xffffffffu, px0, 2));
            px1 = fmaxf(px1, __shfl_xor_sync(0xffffffffu, px1, 1));
            px1 = fmaxf(px1, __shfl_xor_sync(0xffffffffu, px1, 2));
            const float mn0 = fmaxf(mr0, px0), mn1 = fmaxf(mr1, px1);
            const float cr0 = __expf(mr0 - mn0), cr1 = __expf(mr1 - mn1);
            mr0 = mn0; mr1 = mn1;
            float s0 = 0.f, s1 = 0.f;
#pragma unroll
            for (int nt = 0; nt < 8; nt++) {
                const float p0 = __expf(sf[nt][0] - mn0);
                const float p1 = __expf(sf[nt][1] - mn0);
                const float p2 = __expf(sf[nt][2] - mn1);
                const float p3 = __expf(sf[nt][3] - mn1);
                s0 += p0 + p1; s1 += p2 + p3;
                const int col = nt * 8 + qd * 2;
                *(half2*)(sm + S_P + (slice + g) * PSTR + col * 2)     = __floats2half2_rn(p0, p1);
                *(half2*)(sm + S_P + (slice + g + 8) * PSTR + col * 2) = __floats2half2_rn(p2, p3);
            }
            s0 += __shfl_xor_sync(0xffffffffu, s0, 1);
            s0 += __shfl_xor_sync(0xffffffffu, s0, 2);
            s1 += __shfl_xor_sync(0xffffffffu, s1, 1);
            s1 += __shfl_xor_sync(0xffffffffu, s1, 2);
            l0 = l0 * cr0 + s0;
            l1 = l1 * cr1 + s1;
            if (qd == 0) { corr_s[slice + g] = cr0; corr_s[slice + g + 8] = cr1; }
        }
        asm volatile("cp.async.wait_group 0;");
        __syncthreads();

        {
            const float c0 = corr_s[slice + g], c1 = corr_s[slice + g + 8];
#pragma unroll
            for (int j = 0; j < 16; j++) {
                of[j][0] *= c0; of[j][1] *= c0; of[j][2] *= c1; of[j][3] *= c1;
            }
        }
#pragma unroll
        for (int kc = 0; kc < 4; kc++) {
            uint32_t pa[4];
            ldsm4(pa, sb + S_P + (slice + (lane & 15)) * PSTR + kc * 32 + (lane >> 4) * 16);
            const int key = kc * 16 + (lane & 7) + ((lane >> 3) & 1) * 8;
#pragma unroll
            for (int jj = 0; jj < 8; jj++) {
                uint32_t vb[4];
                ldsm4t(vb, sb + S_KV + key * QSTR + (doff + jj * 16) * 2 + ((lane >> 4) & 1) * 16);
                mma_f16(of[2 * jj],     pa, vb[0], vb[1]);
                mma_f16(of[2 * jj + 1], pa, vb[2], vb[3]);
            }
        }
        __syncthreads();
    }

    if (grp == 0 && qd == 0) {
        linv_s[slice + g]     = 1.f / l0;
        linv_s[slice + g + 8] = 1.f / l1;
    }
    __syncthreads();
    const float ia = linv_s[slice + g], ib = linv_s[slice + g + 8];
    const int row0 = m0 + slice + g;
#pragma unroll
    for (int nt = 0; nt < 16; nt++) {
        const int col = cb + doff + nt * 8 + qd * 2;
        ((half2*)Oh)[((size_t)row0 * EMBED + col) >> 1] =
            __floats2half2_rn(of[nt][0] * ia, of[nt][1] * ia);
        ((half2*)Oh)[((size_t)(row0 + 8) * EMBED + col) >> 1] =
            __floats2half2_rn(of[nt][2] * ib, of[nt][3] * ib);
    }
}

// ==============================================================================
// launch
// ==============================================================================
extern "C" void kernel_launch(void* const* d_in, const int* in_sizes, int n_in,
                              void* d_out, int out_size)
{
    (void)in_sizes; (void)n_in; (void)out_size;
    const float* X  = (const float*)d_in[0];
    const float* Wq = (const float*)d_in[1];
    const float* Wk = (const float*)d_in[2];
    const float* Wv = (const float*)d_in[3];
    const float* Wo = (const float*)d_in[4];
    float* out = (float*)d_out;

    __half *qh, *kh, *vh, *ah, *wqh, *wkh, *wvh, *woh;
    cudaGetSymbolAddress((void**)&qh,  g_qh);
    cudaGetSymbolAddress((void**)&kh,  g_kh);
    cudaGetSymbolAddress((void**)&vh,  g_vh);
    cudaGetSymbolAddress((void**)&ah,  g_ah);
    cudaGetSymbolAddress((void**)&wqh, g_wqh);
    cudaGetSymbolAddress((void**)&wkh, g_wkh);
    cudaGetSymbolAddress((void**)&wvh, g_wvh);
    cudaGetSymbolAddress((void**)&woh, g_woh);

    cudaFuncSetAttribute(gemm_f16_out,
                         cudaFuncAttributeMaxDynamicSharedMemorySize, GEMM_SMEM);
    cudaFuncSetAttribute(gemm_f16_qkv,
                         cudaFuncAttributeMaxDynamicSharedMemorySize, GEMM_SMEM);
    cudaFuncSetAttribute(attn_mma,
                         cudaFuncAttributeMaxDynamicSharedMemorySize, ATT_SMEM);

    const int CVB = NELEM / 8 / 256;        // 2 x float4 per thread
    dim3 gc(CVB, 5);
    cvt_f16_multi<<<gc, 256>>>(X, ah, Wq, wqh, Wk, wkh, Wv, wvh, Wo, woh);

    dim3 gq(4096 / 128, 4096 / 128, 3);    // (32, 32, 3)
    gemm_f16_qkv<<<gq, GTHR, GEMM_SMEM>>>(ah, wqh, wkh, wvh, qh, kh, vh);

    dim3 ga(SEQ / 64, HEADS);
    attn_mma<<<ga, 256, ATT_SMEM>>>(qh, kh, vh, ah);

    dim3 gg(4096 / 128, 4096 / 128);       // (32, 32)
    gemm_f16_out<<<gg, GTHR, GEMM_SMEM>>>(ah, woh, out);
}

// round 17
// speedup vs baseline: 1.5619x; 1.0013x over previous
#include <cuda_runtime.h>
#include <cuda_fp16.h>
#include <math.h>
#include <stdint.h>

#define SEQ   4096
#define EMBED 4096
#define HEADS 16
#define HD    256
#define ROT   64
#define NELEM (SEQ * EMBED)

// ---------------- scratch (allocation-free rule: __device__ globals) ----------
__device__ __half g_qh [NELEM];
__device__ __half g_kh [NELEM];
__device__ __half g_vh [NELEM];
__device__ __half g_ah [NELEM];
__device__ __half g_wqh[NELEM];
__device__ __half g_wkh[NELEM];
__device__ __half g_wvh[NELEM];
__device__ __half g_woh[NELEM];
__device__ float2 g_rope[SEQ * 32];        // (sin, cos) per (row, j)

// ==============================================================================
// helpers
// ==============================================================================
__device__ __forceinline__ void cp16(uint32_t dst, const void* src) {
    asm volatile("cp.async.cg.shared.global [%0], [%1], 16;" :: "r"(dst), "l"(src));
}

__device__ __forceinline__ void ldsm4(uint32_t* r, uint32_t a) {
    asm volatile("ldmatrix.sync.aligned.m8n8.x4.shared.b16 {%0,%1,%2,%3}, [%4];"
                 : "=r"(r[0]), "=r"(r[1]), "=r"(r[2]), "=r"(r[3]) : "r"(a));
}

__device__ __forceinline__ void ldsm4t(uint32_t* r, uint32_t a) {
    asm volatile("ldmatrix.sync.aligned.m8n8.x4.trans.shared.b16 {%0,%1,%2,%3}, [%4];"
                 : "=r"(r[0]), "=r"(r[1]), "=r"(r[2]), "=r"(r[3]) : "r"(a));
}

__device__ __forceinline__ void mma_f16(float* c, const uint32_t* a,
                                        uint32_t b0, uint32_t b1) {
    asm volatile(
        "mma.sync.aligned.m16n8k16.row.col.f32.f16.f16.f32 "
        "{%0,%1,%2,%3}, {%4,%5,%6,%7}, {%8,%9}, {%0,%1,%2,%3};"
        : "+f"(c[0]), "+f"(c[1]), "+f"(c[2]), "+f"(c[3])
        : "r"(a[0]), "r"(a[1]), "r"(a[2]), "r"(a[3]), "r"(b0), "r"(b1));
}

// ==============================================================================
// RoPE sin/cos table: identical formula to round-16 epilogue -> bitwise-same
// ==============================================================================
__global__ void rope_table()
{
    const int i = blockIdx.x * blockDim.x + threadIdx.x;   // SEQ*32
    const int row = i >> 5, j = i & 31;
    const float inv = exp2f((float)j * -0.41524101186092f);
    float sn, cs;
    sincosf((float)row * inv, &sn, &cs);
    g_rope[i] = make_float2(sn, cs);
}

// ==============================================================================
// fused fp32 -> fp16 conversion: y-dim selects tensor; 2 x float4 per thread
// ==============================================================================
__global__ void cvt_f16_multi(const float* __restrict__ x0, __half* __restrict__ y0,
                              const float* __restrict__ x1, __half* __restrict__ y1,
                              const float* __restrict__ x2, __half* __restrict__ y2,
                              const float* __restrict__ x3, __half* __restrict__ y3,
                              const float* __restrict__ x4, __half* __restrict__ y4)
{
    const int z = blockIdx.y;
    const float* x = (z == 0) ? x0 : (z == 1) ? x1 : (z == 2) ? x2 : (z == 3) ? x3 : x4;
    __half*      y = (z == 0) ? y0 : (z == 1) ? y1 : (z == 2) ? y2 : (z == 3) ? y3 : y4;
    const int i = blockIdx.x * blockDim.x + threadIdx.x;
#pragma unroll
    for (int u = 0; u < 2; u++) {
        const int e = 2 * i + u;
        float4 v = ((const float4*)x)[e];
        ((half2*)y)[2 * e]     = __floats2half2_rn(v.x, v.y);
        ((half2*)y)[2 * e + 1] = __floats2half2_rn(v.z, v.w);
    }
}

// ==============================================================================
// RoPE rotation on an fp32 column pair (col even) via precomputed table
// ==============================================================================
__device__ __forceinline__ void rope2(float& c0, float& c1, int row, int col)
{
    const int hd = col & 255;
    if (hd < ROT) {
        const float2 sc = g_rope[(row << 5) + (hd >> 1)];
        const float x = c0, y = c1;
        c0 = x * sc.y - y * sc.x;
        c1 = y * sc.y + x * sc.x;
    }
}

// ==============================================================================
// fp16 tensor-core GEMM (NT): C = A * B^T. 128x128 block, BK=64, 3-stage
// cp.async pipeline, 8 warps (256 thr), warp tile 32x64, 128 regs/thread,
// 110.6KB smem -> TWO CTAs per SM. (round-16 config; epilogue now table-based)
// epilogue modes: 0 = fp32 C, 1 = rope + fp16, 2 = fp16 plain
// ==============================================================================
#define HSTR  144
#define SOFFB (128 * HSTR)                  // 18432
#define SSTG  (256 * HSTR)                  // 36864 per stage
#define GEMM_SMEM (3 * SSTG)                // 110592
#define GTHR  256

__device__ __forceinline__ void gemm_body(const __half* __restrict__ A,
                                          const __half* __restrict__ B,
                                          uint32_t sb, int m0, int n0,
                                          int mode, float* Cf, __half* Ch)
{
    const int tid  = threadIdx.x;
    const int lane = tid & 31;
    const int warp = tid >> 5;
    const int wm   = warp & 3;              // 32-row slab (4)
    const int wn   = warp >> 2;             // 64-col slab (2)

    float acc[2][8][4];
#pragma unroll
    for (int i = 0; i < 2; i++)
#pragma unroll
        for (int j = 0; j < 8; j++)
#pragma unroll
            for (int r = 0; r < 4; r++) acc[i][j][r] = 0.f;

    auto load_stage = [&](int stage, int kt) {
        const uint32_t st = sb + stage * SSTG;
#pragma unroll
        for (int i = 0; i < 4; i++) {
            const int f = tid + 256 * i;
            const int r = f >> 3, c = f & 7;
            cp16(st + r * HSTR + c * 16,
                 A + (size_t)(m0 + r) * 4096 + kt + c * 8);
            cp16(st + SOFFB + r * HSTR + c * 16,
                 B + (size_t)(n0 + r) * 4096 + kt + c * 8);
        }
        asm volatile("cp.async.commit_group;");
    };

    load_stage(0, 0);
    load_stage(1, 64);

    const uint32_t arow = (lane & 15) * HSTR + (lane >> 4) * 16;
    const uint32_t brow = ((lane & 7) + ((lane >> 4) & 1) * 8) * HSTR
                        + ((lane >> 3) & 1) * 16;
    const int NT = 4096 / 64;   // 64

    int stage = 0;
    for (int t = 0; t < NT; t++) {
        if (t < NT - 1) asm volatile("cp.async.wait_group 1;");
        else            asm volatile("cp.async.wait_group 0;");
        __syncthreads();
        if (t + 2 < NT) {
            int ns = stage + 2; if (ns >= 3) ns -= 3;
            load_stage(ns, (t + 2) * 64);
        }

        const uint32_t ab = sb + stage * SSTG + (wm * 32) * HSTR;
        const uint32_t bb = sb + stage * SSTG + SOFFB + (wn * 64) * HSTR;

#pragma unroll
        for (int ks = 0; ks < 4; ks++) {
            const int kb = ks * 32;
            uint32_t af[2][4], bf[4][4];
            ldsm4(af[0], ab + arow + kb);
            ldsm4(af[1], ab + 16 * HSTR + arow + kb);
            ldsm4(bf[0], bb + brow + kb);
            ldsm4(bf[1], bb + 16 * HSTR + brow + kb);
            ldsm4(bf[2], bb + 32 * HSTR + brow + kb);
            ldsm4(bf[3], bb + 48 * HSTR + brow + kb);
#pragma unroll
            for (int np = 0; np < 4; np++)
#pragma unroll
                for (int mt = 0; mt < 2; mt++) {
                    mma_f16(acc[mt][np * 2],     af[mt], bf[np][0], bf[np][1]);
                    mma_f16(acc[mt][np * 2 + 1], af[mt], bf[np][2], bf[np][3]);
                }
        }
        if (++stage == 3) stage = 0;
    }

    const int g  = lane >> 2;
    const int qd = lane & 3;
#pragma unroll
    for (int mt = 0; mt < 2; mt++) {
        const int r0 = m0 + wm * 32 + mt * 16 + g;
#pragma unroll
        for (int nt = 0; nt < 8; nt++) {
            const int col = n0 + wn * 64 + nt * 8 + qd * 2;
#pragma unroll
            for (int half = 0; half < 2; half++) {
                const int row = r0 + half * 8;
                float c0 = acc[mt][nt][half * 2], c1 = acc[mt][nt][half * 2 + 1];
                if (mode == 0) {
                    *(float2*)&Cf[(size_t)row * 4096 + col] = make_float2(c0, c1);
                } else if (mode == 1) {
                    rope2(c0, c1, row, col);
                    ((half2*)Ch)[((size_t)row * 4096 + col) >> 1] =
                        __floats2half2_rn(c0, c1);
                } else {
                    ((half2*)Ch)[((size_t)row * 4096 + col) >> 1] =
                        __floats2half2_rn(c0, c1);
                }
            }
        }
    }
}

__global__ __launch_bounds__(GTHR, 2)
void gemm_f16_out(const __half* __restrict__ A, const __half* __restrict__ B,
                  float* __restrict__ C)
{
    extern __shared__ __align__(16) char smg[];
    gemm_body(A, B, (uint32_t)__cvta_generic_to_shared(smg),
              blockIdx.y * 128, blockIdx.x * 128, 0, C, nullptr);
}

__global__ __launch_bounds__(GTHR, 2)
void gemm_f16_qkv(const __half* __restrict__ A,
                  const __half* __restrict__ Bq, const __half* __restrict__ Bk,
                  const __half* __restrict__ Bv,
                  __half* __restrict__ qh, __half* __restrict__ kh,
                  __half* __restrict__ vh)
{
    extern __shared__ __align__(16) char smg[];
    const int z = blockIdx.z;
    const __half* B = (z == 0) ? Bq : (z == 1) ? Bk : Bv;
    __half* C      = (z == 0) ? qh : (z == 1) ? kh : vh;
    gemm_body(A, B, (uint32_t)__cvta_generic_to_shared(smg),
              blockIdx.y * 128, blockIdx.x * 128, (z == 2) ? 2 : 1,
              nullptr, C);
}

// ==============================================================================
// Tensor-core causal flash attention (round-14/16 version, validated).
// QK: single fp16 product. PV: fp16. Softmax fp32. K/V share one smem buffer;
// 94.7KB smem -> 2 CTAs/SM.
// ==============================================================================
#define QSTR 528
#define PSTR 144
#define S_Q    0
#define S_KV   33792
#define S_SB   67584
#define S_P    84992
#define S_CORR 94208
#define S_LINV 94464
#define ATT_SMEM 94720

__global__ __launch_bounds__(256, 2)
void attn_mma(const __half* __restrict__ Qh, const __half* __restrict__ Kh,
              const __half* __restrict__ Vh, __half* __restrict__ Oh)
{
    extern __shared__ __align__(16) char sm[];
    const uint32_t sb = (uint32_t)__cvta_generic_to_shared(sm);
    float* SBf    = (float*)(sm + S_SB);
    float* corr_s = (float*)(sm + S_CORR);
    float* linv_s = (float*)(sm + S_LINV);

    const int tid   = threadIdx.x;
    const int lane  = tid & 31;
    const int wid   = tid >> 5;
    const int grp   = wid >> 2;
    const int slice = (wid & 3) * 16;
    const int g     = lane >> 2;
    const int qd    = lane & 3;

    const int h    = blockIdx.y;
    const int m0   = ((int)gridDim.x - 1 - (int)blockIdx.x) * 64;
    const int cb   = h * HD;
    const int doff = grp * 128;

    for (int f = tid; f < 2048; f += 256) {
        const int r = f >> 5, c = f & 31;
        cp16(sb + S_Q + r * QSTR + c * 16,
             Qh + (size_t)(m0 + r) * EMBED + cb + c * 8);
    }

    float of[16][4];
#pragma unroll
    for (int j = 0; j < 16; j++)
#pragma unroll
        for (int r = 0; r < 4; r++) of[j][r] = 0.f;
    float mr0 = -1e30f, mr1 = -1e30f, l0 = 0.f, l1 = 0.f;

    const int ntl = m0 / 64 + 1;
    for (int t = 0; t < ntl; t++) {
        const int n0 = t * 64;

        for (int f = tid; f < 2048; f += 256) {
            const int r = f >> 5, c = f & 31;
            cp16(sb + S_KV + r * QSTR + c * 16,
                 Kh + (size_t)(n0 + r) * EMBED + cb + c * 8);
        }
        asm volatile("cp.async.commit_group;");
        asm volatile("cp.async.wait_group 0;");
        __syncthreads();

        float sf[8][4];
#pragma unroll
        for (int nt = 0; nt < 8; nt++)
#pragma unroll
            for (int r = 0; r < 4; r++) sf[nt][r] = 0.f;

        const uint32_t qa = sb + S_Q + (slice + (lane & 15)) * QSTR + (lane >> 4) * 16;
#pragma unroll
        for (int kc = 0; kc < 8; kc++) {
            const int dby = (doff + kc * 16) * 2;
            uint32_t qf[4];
            ldsm4(qf, qa + dby);
#pragma unroll
            for (int kg = 0; kg < 4; kg++) {
                const int key = kg * 16 + (lane & 7) + ((lane >> 4) & 1) * 8;
                const uint32_t ba = sb + S_KV + key * QSTR + dby + ((lane >> 3) & 1) * 16;
                uint32_t kf[4];
                ldsm4(kf, ba);
                mma_f16(sf[2 * kg],     qf, kf[0], kf[1]);
                mma_f16(sf[2 * kg + 1], qf, kf[2], kf[3]);
            }
        }

        if (grp == 1) {
#pragma unroll
            for (int nt = 0; nt < 8; nt++) {
                const int col = nt * 8 + qd * 2;
                *(float2*)&SBf[(slice + g) * 68 + col]     = make_float2(sf[nt][0], sf[nt][1]);
                *(float2*)&SBf[(slice + g + 8) * 68 + col] = make_float2(sf[nt][2], sf[nt][3]);
            }
        }
        __syncthreads();

        for (int f = tid; f < 2048; f += 256) {
            const int r = f >> 5, c = f & 31;
            cp16(sb + S_KV + r * QSTR + c * 16,
                 Vh + (size_t)(n0 + r) * EMBED + cb + c * 8);
        }
        asm volatile("cp.async.commit_group;");

        if (grp == 0) {
            const int row0 = m0 + slice + g, row1 = row0 + 8;
            float px0 = -1e30f, px1 = -1e30f;
#pragma unroll
            for (int nt = 0; nt < 8; nt++) {
                const int col = nt * 8 + qd * 2;
                const float2 b0 = *(float2*)&SBf[(slice + g) * 68 + col];
                const float2 b1 = *(float2*)&SBf[(slice + g + 8) * 68 + col];
                const int cg = n0 + col;
                sf[nt][0] = (cg     <= row0) ? (sf[nt][0] + b0.x) * 0.0625f : -1e30f;
                sf[nt][1] = (cg + 1 <= row0) ? (sf[nt][1] + b0.y) * 0.0625f : -1e30f;
                sf[nt][2] = (cg     <= row1) ? (sf[nt][2] + b1.x) * 0.0625f : -1e30f;
                sf[nt][3] = (cg + 1 <= row1) ? (sf[nt][3] + b1.y) * 0.0625f : -1e30f;
                px0 = fmaxf(px0, fmaxf(sf[nt][0], sf[nt][1]));
                px1 = fmaxf(px1, fmaxf(sf[nt][2], sf[nt][3]));
            }
            px0 = fmaxf(px0, __shfl_xor_sync(0xffffffffu, px0, 1));
            px0 = fmaxf(px0, __shfl_xor_sync(0xffffffffu, px0, 2));
            px1 = fmaxf(px1, __shfl_xor_sync(0xffffffffu, px1, 1));
            px1 = fmaxf(px1, __shfl_xor_sync(0xffffffffu, px1, 2));
            const float mn0 = fmaxf(mr0, px0), mn1 = fmaxf(mr1, px1);
            const float cr0 = __expf(mr0 - mn0), cr1 = __expf(mr1 - mn1);
            mr0 = mn0; mr1 = mn1;
            float s0 = 0.f, s1 = 0.f;
#pragma unroll
            for (int nt = 0; nt < 8; nt++) {
                const float p0 = __expf(sf[nt][0] - mn0);
                const float p1 = __expf(sf[nt][1] - mn0);
                const float p2 = __expf(sf[nt][2] - mn1);
                const float p3 = __expf(sf[nt][3] - mn1);
                s0 += p0 + p1; s1 += p2 + p3;
                const int col = nt * 8 + qd * 2;
                *(half2*)(sm + S_P + (slice + g) * PSTR + col * 2)     = __floats2half2_rn(p0, p1);
                *(half2*)(sm + S_P + (slice + g + 8) * PSTR + col * 2) = __floats2half2_rn(p2, p3);
            }
            s0 += __shfl_xor_sync(0xffffffffu, s0, 1);
            s0 += __shfl_xor_sync(0xffffffffu, s0, 2);
            s1 += __shfl_xor_sync(0xffffffffu, s1, 1);
            s1 += __shfl_xor_sync(0xffffffffu, s1, 2);
            l0 = l0 * cr0 + s0;
            l1 = l1 * cr1 + s1;
            if (qd == 0) { corr_s[slice + g] = cr0; corr_s[slice + g + 8] = cr1; }
        }
        asm volatile("cp.async.wait_group 0;");
        __syncthreads();

        {
            const float c0 = corr_s[slice + g], c1 = corr_s[slice + g + 8];
#pragma unroll
            for (int j = 0; j < 16; j++) {
                of[j][0] *= c0; of[j][1] *= c0; of[j][2] *= c1; of[j][3] *= c1;
            }
        }
#pragma unroll
        for (int kc = 0; kc < 4; kc++) {
            uint32_t pa[4];
            ldsm4(pa, sb + S_P + (slice + (lane & 15)) * PSTR + kc * 32 + (lane >> 4) * 16);
            const int key = kc * 16 + (lane & 7) + ((lane >> 3) & 1) * 8;
#pragma unroll
            for (int jj = 0; jj < 8; jj++) {
                uint32_t vb[4];
                ldsm4t(vb, sb + S_KV + key * QSTR + (doff + jj * 16) * 2 + ((lane >> 4) & 1) * 16);
                mma_f16(of[2 * jj],     pa, vb[0], vb[1]);
                mma_f16(of[2 * jj + 1], pa, vb[2], vb[3]);
            }
        }
        __syncthreads();
    }

    if (grp == 0 && qd == 0) {
        linv_s[slice + g]     = 1.f / l0;
        linv_s[slice + g + 8] = 1.f / l1;
    }
    __syncthreads();
    const float ia = linv_s[slice + g], ib = linv_s[slice + g + 8];
    const int row0 = m0 + slice + g;
#pragma unroll
    for (int nt = 0; nt < 16; nt++) {
        const int col = cb + doff + nt * 8 + qd * 2;
        ((half2*)Oh)[((size_t)row0 * EMBED + col) >> 1] =
            __floats2half2_rn(of[nt][0] * ia, of[nt][1] * ia);
        ((half2*)Oh)[((size_t)(row0 + 8) * EMBED + col) >> 1] =
            __floats2half2_rn(of[nt][2] * ib, of[nt][3] * ib);
    }
}

// ==============================================================================
// launch
// ==============================================================================
extern "C" void kernel_launch(void* const* d_in, const int* in_sizes, int n_in,
                              void* d_out, int out_size)
{
    (void)in_sizes; (void)n_in; (void)out_size;
    const float* X  = (const float*)d_in[0];
    const float* Wq = (const float*)d_in[1];
    const float* Wk = (const float*)d_in[2];
    const float* Wv = (const float*)d_in[3];
    const float* Wo = (const float*)d_in[4];
    float* out = (float*)d_out;

    __half *qh, *kh, *vh, *ah, *wqh, *wkh, *wvh, *woh;
    cudaGetSymbolAddress((void**)&qh,  g_qh);
    cudaGetSymbolAddress((void**)&kh,  g_kh);
    cudaGetSymbolAddress((void**)&vh,  g_vh);
    cudaGetSymbolAddress((void**)&ah,  g_ah);
    cudaGetSymbolAddress((void**)&wqh, g_wqh);
    cudaGetSymbolAddress((void**)&wkh, g_wkh);
    cudaGetSymbolAddress((void**)&wvh, g_wvh);
    cudaGetSymbolAddress((void**)&woh, g_woh);

    cudaFuncSetAttribute(gemm_f16_out,
                         cudaFuncAttributeMaxDynamicSharedMemorySize, GEMM_SMEM);
    cudaFuncSetAttribute(gemm_f16_qkv,
                         cudaFuncAttributeMaxDynamicSharedMemorySize, GEMM_SMEM);
    cudaFuncSetAttribute(attn_mma,
                         cudaFuncAttributeMaxDynamicSharedMemorySize, ATT_SMEM);

    rope_table<<<SEQ * 32 / 256, 256>>>();

    const int CVB = NELEM / 8 / 256;        // 2 x float4 per thread
    dim3 gc(CVB, 5);
    cvt_f16_multi<<<gc, 256>>>(X, ah, Wq, wqh, Wk, wkh, Wv, wvh, Wo, woh);

    dim3 gq(4096 / 128, 4096 / 128, 3);    // (32, 32, 3)
    gemm_f16_qkv<<<gq, GTHR, GEMM_SMEM>>>(ah, wqh, wkh, wvh, qh, kh, vh);

    dim3 ga(SEQ / 64, HEADS);
    attn_mma<<<ga, 256, ATT_SMEM>>>(qh, kh, vh, ah);

    dim3 gg(4096 / 128, 4096 / 128);       // (32, 32)
    gemm_f16_out<<<gg, GTHR, GEMM_SMEM>>>(ah, woh, out);
}